// round 10
// baseline (speedup 1.0000x reference)
#include <cuda_runtime.h>

// out[b, i, f] = x[b, i] * W[i, f] + bias[i, f]
// BS=16384, DEMO_DIM=32, FEAT_DIM=256 -> 512 MiB fp32 out. Pure HBM-store-bound.
//
// Round-6 changes vs round-3 (74.2us, DRAM=80.4%):
//  - BPT 8 -> 16: grid 16384 -> 8192 CTAs (~14 -> ~7 waves), halves
//    wave-transition + tail overhead. W/b register reuse now 16x.
//  - Front-batch all 16 x loads (independent LDGs, MLP=16) before the
//    store burst so the LSU queue is store-dominated in steady state.
//  - Keep __stcs streaming stores (write-once output, evict-first).

#define BS        16384
#define DEMO_DIM  32
#define FEAT_DIM  256
#define F4        (FEAT_DIM / 4)                 // 64 float4 per (b,i)
#define ROW4      (DEMO_DIM * F4)                // 2048 float4 per batch
#define BPT       16                             // batches per thread
#define THREADS   256
#define OFF_CHUNKS (ROW4 / THREADS)              // 8 chunks of 256 float4 per row
#define NBLOCKS   ((BS / BPT) * OFF_CHUNKS)      // 1024 * 8 = 8192 blocks

__global__ __launch_bounds__(THREADS) void demo_proj_kernel(
    const float*  __restrict__ x,     // [BS, DEMO_DIM]
    const float4* __restrict__ W4,    // [DEMO_DIM, F4]
    const float4* __restrict__ B4,    // [DEMO_DIM, F4]
    float4*       __restrict__ out4)  // [BS, DEMO_DIM, F4]
{
    // Low 3 bits of blockIdx pick the 256-float4 chunk within the
    // 2048-float4 row; high bits pick the group of BPT batches.
    int off_chunk = blockIdx.x & (OFF_CHUNKS - 1);
    int bgroup    = blockIdx.x >> 3;

    int off = off_chunk * THREADS + threadIdx.x;   // 0..2047, fixed per thread
    int i   = off >> 6;                            // demo index, fixed
    int f4  = off & (F4 - 1);                      // feature chunk, fixed

    // Per-thread W/b loaded ONCE; reused for all BPT batches.
    float4 w  = __ldg(&W4[i * F4 + f4]);
    float4 bv = __ldg(&B4[i * F4 + f4]);

    int bb0 = bgroup * BPT;
    const float* xrow = x + bb0 * DEMO_DIM + i;
    float4* dst = out4 + (long long)bb0 * ROW4 + off;

    // Front-batch the 16 independent x loads (MLP) — all L1 broadcast hits
    // after the first wave.
    float xv[BPT];
#pragma unroll
    for (int k = 0; k < BPT; k++)
        xv[k] = __ldg(xrow + k * DEMO_DIM);

#pragma unroll
    for (int k = 0; k < BPT; k++) {
        float4 o;
        o.x = fmaf(xv[k], w.x, bv.x);
        o.y = fmaf(xv[k], w.y, bv.y);
        o.z = fmaf(xv[k], w.z, bv.z);
        o.w = fmaf(xv[k], w.w, bv.w);
        __stcs(dst + (long long)k * ROW4, o);      // streaming, warp-coalesced
    }
}

extern "C" void kernel_launch(void* const* d_in, const int* in_sizes, int n_in,
                              void* d_out, int out_size)
{
    const float*  x  = (const float*)d_in[0];
    const float4* W4 = (const float4*)d_in[1];
    const float4* B4 = (const float4*)d_in[2];
    float4* out4 = (float4*)d_out;

    demo_proj_kernel<<<NBLOCKS, THREADS>>>(x, W4, B4, out4);
}

// round 11
// speedup vs baseline: 1.0051x; 1.0051x over previous
#include <cuda_runtime.h>

// out[b, i, f] = x[b, i] * W[i, f] + bias[i, f]
// BS=16384, DEMO_DIM=32, FEAT_DIM=256 -> 512 MiB fp32 out. Pure HBM-store-bound.
//
// Round-10: REVERT to the round-3 configuration (74.2us, DRAM=80.4%, occ=92.7%).
// Round-6's BPT=16 experiment regressed (75.7us): regs 32->40 and grid 8192
// dropped occupancy to 69.5%; wave-transition overhead was not the binding
// term. Binding resource = DRAM write BW, maximized by concurrent store
// pressure (high occupancy, short dep chains).
//
//  - BPT=8 batches per thread, fixed (i, f4): W/b in registers, 8x reuse.
//  - 16384 CTAs x 256 threads, 32 regs -> occ ~93%.
//  - __stcs streaming stores (write-once output, evict-first).
//  - Interleaved load->fma->store per iteration (scoreboard overlaps the
//    uniform x load of iteration k+1 with the store of iteration k).

#define BS        16384
#define DEMO_DIM  32
#define FEAT_DIM  256
#define F4        (FEAT_DIM / 4)                 // 64 float4 per (b,i)
#define ROW4      (DEMO_DIM * F4)                // 2048 float4 per batch
#define BPT       8                              // batches per thread
#define THREADS   256
#define OFF_CHUNKS (ROW4 / THREADS)              // 8 chunks of 256 float4 per row
#define NBLOCKS   ((BS / BPT) * OFF_CHUNKS)      // 2048 * 8 = 16384 blocks

__global__ __launch_bounds__(THREADS) void demo_proj_kernel(
    const float*  __restrict__ x,     // [BS, DEMO_DIM]
    const float4* __restrict__ W4,    // [DEMO_DIM, F4]
    const float4* __restrict__ B4,    // [DEMO_DIM, F4]
    float4*       __restrict__ out4)  // [BS, DEMO_DIM, F4]
{
    // Low 3 bits of blockIdx pick the 256-float4 chunk within the
    // 2048-float4 row; high bits pick the group of BPT batches.
    unsigned off_chunk = blockIdx.x & (OFF_CHUNKS - 1);
    unsigned bgroup    = blockIdx.x >> 3;

    unsigned off = off_chunk * THREADS + threadIdx.x;   // 0..2047, fixed
    unsigned i   = off >> 6;                            // demo index, fixed
    unsigned f4  = off & (F4 - 1);                      // feature chunk, fixed

    // Per-thread W/b loaded ONCE; reused for all BPT batches.
    float4 w  = __ldg(&W4[i * F4 + f4]);
    float4 bv = __ldg(&B4[i * F4 + f4]);

    unsigned bb0 = bgroup * BPT;
    const float* xrow = x + bb0 * DEMO_DIM + i;
    float4* dst = out4 + (size_t)bb0 * ROW4 + off;

#pragma unroll
    for (int k = 0; k < BPT; k++) {
        float xv = __ldg(xrow + k * DEMO_DIM);   // uniform per warp, L1 hit
        float4 o;
        o.x = fmaf(xv, w.x, bv.x);
        o.y = fmaf(xv, w.y, bv.y);
        o.z = fmaf(xv, w.z, bv.z);
        o.w = fmaf(xv, w.w, bv.w);
        __stcs(dst + (size_t)k * ROW4, o);       // streaming, warp-coalesced
    }
}

extern "C" void kernel_launch(void* const* d_in, const int* in_sizes, int n_in,
                              void* d_out, int out_size)
{
    const float*  x  = (const float*)d_in[0];
    const float4* W4 = (const float4*)d_in[1];
    const float4* B4 = (const float4*)d_in[2];
    float4* out4 = (float4*)d_out;

    demo_proj_kernel<<<NBLOCKS, THREADS>>>(x, W4, B4, out4);
}